// round 3
// baseline (speedup 1.0000x reference)
#include <cuda_runtime.h>
#include <cuda_bf16.h>
#include <math.h>

// Problem constants
#define B    64
#define C    256
#define S    3136          // 56*56
#define S4   784           // S/4
#define HID  196
#define KSEL 1568          // rank of first KEPT element (0-indexed kth smallest)

// K-split for GEMM1
#define KC   32
#define KCH  98            // 3136/32

// Scratch (device globals: no allocation allowed)
__device__ float g_Y[B * S];            // pooled means          [64,3136]
__device__ float g_Hpart[KC * B * HID]; // GEMM1 partials        [32][64*196]
__device__ float g_H[B * HID];          // relu(hidden)          [64,196]
__device__ float g_S[B * S];            // sigmoid outputs       [64,3136]

// ---------------------------------------------------------------------------
// K1: channel-mean pool.  Y[b][s] = mean_c x[b][c][s].  float4 coalesced.
// grid (4, 64), block 256
// ---------------------------------------------------------------------------
__global__ void k_pool(const float* __restrict__ x) {
    int b = blockIdx.y;
    int f = blockIdx.x * blockDim.x + threadIdx.x;   // float4 index 0..783
    if (f >= S4) return;
    const float4* xp = reinterpret_cast<const float4*>(x) + (size_t)b * C * S4 + f;
    float sx = 0.f, sy = 0.f, sz = 0.f, sw = 0.f;
#pragma unroll 8
    for (int c = 0; c < C; c++) {
        float4 v = __ldg(xp + (size_t)c * S4);
        sx += v.x; sy += v.y; sz += v.z; sw += v.w;
    }
    const float inv = 1.0f / (float)C;
    float4 o; o.x = sx * inv; o.y = sy * inv; o.z = sz * inv; o.w = sw * inv;
    reinterpret_cast<float4*>(g_Y)[(size_t)b * S4 + f] = o;
}

// ---------------------------------------------------------------------------
// K2: GEMM1 partials.  Hpart[kc][b][o] = sum_{j in chunk} Y[b][j]*W1[o][j]
// grid (32 kc, 4 o-tiles of 49), block 448 (14 warps).
// sWt [o][j] pitch 100: coalesced fill, broadcast reads in main loop.
// sY  [b][j] pitch 101: conflict-free (gcd(101%32=5,32)=1) lane-varied reads.
// Thread = (b2 = t&63, og = t>>6 in 0..6) accumulates 7 outputs in regs.
// ---------------------------------------------------------------------------
__global__ void k_gemm1(const float* __restrict__ W1) {
    __shared__ float sY[B * 101];        // 25856 B
    __shared__ float sWt[49 * 100];      // 19600 B (45456 total)
    int kc = blockIdx.x;
    int o0 = blockIdx.y * 49;
    int kb = kc * KCH;
    int t = threadIdx.x;

    for (int idx = t; idx < B * KCH; idx += 448) {
        int b2 = idx / KCH, j = idx - b2 * KCH;
        sY[b2 * 101 + j] = g_Y[b2 * S + kb + j];
    }
    for (int idx = t; idx < 49 * KCH; idx += 448) {
        int o = idx / KCH, j = idx - o * KCH;
        sWt[o * 100 + j] = W1[(size_t)(o0 + o) * S + kb + j];
    }
    __syncthreads();

    int b2 = t & 63;
    int og = t >> 6;                     // 0..6
    float acc[7];
#pragma unroll
    for (int k = 0; k < 7; k++) acc[k] = 0.f;
    const float* yr = &sY[b2 * 101];
    const float* wr = &sWt[og * 7 * 100];
#pragma unroll 2
    for (int j = 0; j < KCH; j++) {
        float y = yr[j];
#pragma unroll
        for (int k = 0; k < 7; k++)
            acc[k] = fmaf(y, wr[k * 100 + j], acc[k]);
    }
    int base = kc * (B * HID) + b2 * HID + o0 + og * 7;
#pragma unroll
    for (int k = 0; k < 7; k++) g_Hpart[base + k] = acc[k];
}

// ---------------------------------------------------------------------------
// K3: reduce partials + ReLU, float4.  grid 13, block 256 (3136 float4)
// ---------------------------------------------------------------------------
__global__ void k_redrelu() {
    int f = blockIdx.x * 256 + threadIdx.x;
    if (f >= (B * HID) / 4) return;
    const float4* hp = reinterpret_cast<const float4*>(g_Hpart);
    float4 s = make_float4(0.f, 0.f, 0.f, 0.f);
#pragma unroll
    for (int kc = 0; kc < KC; kc++) {
        float4 v = hp[kc * ((B * HID) / 4) + f];
        s.x += v.x; s.y += v.y; s.z += v.z; s.w += v.w;
    }
    s.x = s.x > 0.f ? s.x : 0.f;
    s.y = s.y > 0.f ? s.y : 0.f;
    s.z = s.z > 0.f ? s.z : 0.f;
    s.w = s.w > 0.f ? s.w : 0.f;
    reinterpret_cast<float4*>(g_H)[f] = s;
}

// ---------------------------------------------------------------------------
// K4: GEMM2 + sigmoid.  S[b][n] = sigmoid( sum_j H[b][j]*W2[n][j] )
// grid (98 n-tiles of 32, 2 b-halves of 32), block 256. Dynamic smem 50176B:
//   sW2 [j][nl] pitch 32 (conflict-free fill + stride-1 main reads)
//   sHT [j][b2] pitch 32 (float4-aligned broadcast main reads)
// Thread = (nl = t&31, bg = t>>5) accumulates 4 b's in regs.
// ---------------------------------------------------------------------------
__global__ void k_gemm2(const float* __restrict__ W2) {
    extern __shared__ float dyn[];
    float* sW2 = dyn;                 // HID*32 floats
    float* sHT = dyn + HID * 32;      // HID*32 floats (offset 25088B, 16B-aligned)
    int n0 = blockIdx.x * 32;
    int b0 = blockIdx.y * 32;
    int t = threadIdx.x;
    int nl = t & 31;
    int bg = t >> 5;

    // fill sW2: lane nl owns row n0+nl, reads it as float4 chunks (MLP ~6)
    for (int idx = t; idx < (HID / 4) * 32; idx += 256) {
        int jq = idx >> 5;                  // 0..48, lane-invariant per iter
        int ln = idx & 31;
        float4 w = *reinterpret_cast<const float4*>(&W2[(size_t)(n0 + ln) * HID + jq * 4]);
        sW2[(jq * 4 + 0) * 32 + ln] = w.x;
        sW2[(jq * 4 + 1) * 32 + ln] = w.y;
        sW2[(jq * 4 + 2) * 32 + ln] = w.z;
        sW2[(jq * 4 + 3) * 32 + ln] = w.w;
    }
    // fill sHT transposed: conflict-free stores, L2-resident strided reads
    for (int idx = t; idx < HID * 32; idx += 256) {
        int b2 = idx & 31, j = idx >> 5;
        sHT[j * 32 + b2] = g_H[(b0 + b2) * HID + j];
    }
    __syncthreads();

    float a0 = 0.f, a1 = 0.f, a2 = 0.f, a3 = 0.f;
#pragma unroll 4
    for (int j = 0; j < HID; j++) {
        float w = sW2[j * 32 + nl];
        float4 h = *reinterpret_cast<const float4*>(&sHT[j * 32 + bg * 4]);
        a0 = fmaf(h.x, w, a0); a1 = fmaf(h.y, w, a1);
        a2 = fmaf(h.z, w, a2); a3 = fmaf(h.w, w, a3);
    }
    int b = b0 + bg * 4;
    int n = n0 + nl;
    g_S[(size_t)(b + 0) * S + n] = 1.0f / (1.0f + expf(-a0));
    g_S[(size_t)(b + 1) * S + n] = 1.0f / (1.0f + expf(-a1));
    g_S[(size_t)(b + 2) * S + n] = 1.0f / (1.0f + expf(-a2));
    g_S[(size_t)(b + 3) * S + n] = 1.0f / (1.0f + expf(-a3));
}

// ---------------------------------------------------------------------------
// K5: exact rank-1568 selection per row (stable-argsort semantics) FUSED with
// the 256-plane broadcast write.  Sigmoid outputs > 0 => uint order == value
// order.  4-pass radix select with warp-shuffle scans; masking in smem; then
// float4 broadcast directly to d_out.  grid 64, block 256.
// ---------------------------------------------------------------------------
__global__ void k_select_bcast(float* __restrict__ out) {
    __shared__ __align__(16) float sv[S];
    __shared__ unsigned int hist[256];
    __shared__ unsigned int wsum[8];
    __shared__ unsigned int sh_pref, sh_r;
    int b = blockIdx.x, t = threadIdx.x;
    int lane = t & 31, wid = t >> 5;

    // load row (float4)
    {
        const float4* src = reinterpret_cast<const float4*>(g_S) + (size_t)b * S4;
        float4* dst = reinterpret_cast<float4*>(sv);
        for (int f = t; f < S4; f += 256) dst[f] = src[f];
    }
    if (t == 0) { sh_pref = 0u; sh_r = KSEL; }
    __syncthreads();

    // radix select: find bit pattern T of the KSEL-th smallest value
    for (int shift = 24; shift >= 0; shift -= 8) {
        hist[t] = 0u;
        __syncthreads();
        unsigned pref = sh_pref;
        unsigned r    = sh_r;
        unsigned hm   = (shift == 24) ? 0u : (0xFFFFFFFFu << (shift + 8));
        for (int i = t; i < S; i += 256) {
            unsigned u = __float_as_uint(sv[i]);
            if ((u & hm) == pref) atomicAdd(&hist[(u >> shift) & 255], 1u);
        }
        __syncthreads();
        unsigned v = hist[t];
        unsigned x = v;
#pragma unroll
        for (int off = 1; off < 32; off <<= 1) {
            unsigned y = __shfl_up_sync(0xFFFFFFFFu, x, off);
            if (lane >= off) x += y;
        }
        if (lane == 31) wsum[wid] = x;
        __syncthreads();
        if (t < 8) {
            unsigned s = wsum[t];
#pragma unroll
            for (int off = 1; off < 8; off <<= 1) {
                unsigned y = __shfl_up_sync(0xFFu, s, off);
                if (t >= off) s += y;
            }
            wsum[t] = s;
        }
        __syncthreads();
        unsigned incl = x + (wid ? wsum[wid - 1] : 0u);
        unsigned excl = incl - v;
        if (v > 0u && r >= excl && r < incl) {   // exactly one thread
            sh_pref = pref | ((unsigned)t << shift);
            sh_r    = r - excl;
        }
        __syncthreads();
    }
    unsigned T    = sh_pref;   // bits of threshold (first KEPT value)
    unsigned rfin = sh_r;      // # of threshold-equal entries (lowest idx) to zero

    // masking in smem: zero u<T; among u==T zero first rfin by ascending index
    int lo = (t * S) >> 8;
    int hi = ((t + 1) * S) >> 8;
    unsigned cnt = 0;
    for (int i = lo; i < hi; i++)
        cnt += (__float_as_uint(sv[i]) == T) ? 1u : 0u;
    unsigned x = cnt;
#pragma unroll
    for (int off = 1; off < 32; off <<= 1) {
        unsigned y = __shfl_up_sync(0xFFFFFFFFu, x, off);
        if (lane >= off) x += y;
    }
    if (lane == 31) wsum[wid] = x;
    __syncthreads();
    if (t < 8) {
        unsigned s = wsum[t];
#pragma unroll
        for (int off = 1; off < 8; off <<= 1) {
            unsigned y = __shfl_up_sync(0xFFu, s, off);
            if (t >= off) s += y;
        }
        wsum[t] = s;
    }
    __syncthreads();
    unsigned e = x - cnt + (wid ? wsum[wid - 1] : 0u);  // exclusive prefix
    for (int i = lo; i < hi; i++) {
        unsigned u = __float_as_uint(sv[i]);
        float val = sv[i];
        if (u < T) val = 0.f;
        else if (u == T) { if (e < rfin) val = 0.f; e++; }
        sv[i] = val;
    }
    __syncthreads();

    // broadcast masked row to all 256 channel planes (float4 stores)
    const float4* sv4 = reinterpret_cast<const float4*>(sv);
    float4* ob = reinterpret_cast<float4*>(out) + (size_t)b * C * S4;
    for (int f = t; f < S4; f += 256) {
        float4 v = sv4[f];
        float4* op = ob + f;
#pragma unroll 8
        for (int c = 0; c < C; c++)
            op[(size_t)c * S4] = v;
    }
}

// ---------------------------------------------------------------------------
extern "C" void kernel_launch(void* const* d_in, const int* in_sizes, int n_in,
                              void* d_out, int out_size) {
    const float* x  = (const float*)d_in[0];
    const float* W1 = (const float*)d_in[1];
    const float* W2 = (const float*)d_in[2];
    float* out = (float*)d_out;

    static int smem_set = 0;
    if (!smem_set) {
        cudaFuncSetAttribute(k_gemm2, cudaFuncAttributeMaxDynamicSharedMemorySize,
                             HID * 64 * (int)sizeof(float));
        smem_set = 1;
    }

    k_pool        <<<dim3(4, B),  256>>>(x);
    k_gemm1       <<<dim3(KC, 4), 448>>>(W1);
    k_redrelu     <<<13,          256>>>();
    k_gemm2       <<<dim3(98, 2), 256, HID * 64 * sizeof(float)>>>(W2);
    k_select_bcast<<<B,           256>>>(out);
}

// round 4
// speedup vs baseline: 1.6967x; 1.6967x over previous
#include <cuda_runtime.h>
#include <cuda_bf16.h>
#include <math.h>

// Problem constants
#define B    64
#define C    256
#define S    3136          // 56*56
#define S4   784           // S/4
#define HID  196
#define KSEL 1568          // rank of first KEPT element (0-indexed kth smallest)

// K-split for GEMM1
#define KC   32
#define KCH  98            // 3136/32

// Scratch (device globals: no allocation allowed)
__device__ float g_Y[B * S];            // pooled means          [64,3136]
__device__ float g_Hpart[KC * B * HID]; // GEMM1 partials        [32][64*196]
__device__ float g_H[B * HID];          // relu(hidden)          [64,196]
__device__ float g_S[B * S];            // sigmoid outputs       [64,3136]
__device__ float g_M[B * S];            // masked row            [64,3136]
__device__ float g_scratch[512 * 8];    // prefetch sink (never read)

// ---------------------------------------------------------------------------
// K0: prefetch W1+W2 into L2 (ld.global.cg = cache at L2).  grid 512, blk 256.
// Sink the sums so loads can't be dead-code-eliminated. Deterministic.
// ---------------------------------------------------------------------------
__global__ void k_prefetch(const float* __restrict__ W1,
                           const float* __restrict__ W2) {
    const int NF4 = (S * HID) / 4;       // 153664 float4 per matrix
    int t = blockIdx.x * 256 + threadIdx.x;
    float s = 0.f;
    const float4* w1 = reinterpret_cast<const float4*>(W1);
    const float4* w2 = reinterpret_cast<const float4*>(W2);
    for (int i = t; i < NF4; i += 512 * 256) {
        float4 a = __ldcg(w1 + i);
        float4 b = __ldcg(w2 + i);
        s += a.x + a.y + a.z + a.w + b.x + b.y + b.z + b.w;
    }
#pragma unroll
    for (int off = 16; off > 0; off >>= 1)
        s += __shfl_down_sync(0xFFFFFFFFu, s, off);
    if ((threadIdx.x & 31) == 0)
        g_scratch[blockIdx.x * 8 + (threadIdx.x >> 5)] = s;
}

// ---------------------------------------------------------------------------
// K1: channel-mean pool.  Y[b][s] = mean_c x[b][c][s].  float4 coalesced.
// __ldcs (evict-first streaming) so the 205MB x stream does not evict the
// L2-resident weights.  grid (4, 64), block 256
// ---------------------------------------------------------------------------
__global__ void k_pool(const float* __restrict__ x) {
    int b = blockIdx.y;
    int f = blockIdx.x * blockDim.x + threadIdx.x;   // float4 index 0..783
    if (f >= S4) return;
    const float4* xp = reinterpret_cast<const float4*>(x) + (size_t)b * C * S4 + f;
    float sx = 0.f, sy = 0.f, sz = 0.f, sw = 0.f;
#pragma unroll 8
    for (int c = 0; c < C; c++) {
        float4 v = __ldcs(xp + (size_t)c * S4);
        sx += v.x; sy += v.y; sz += v.z; sw += v.w;
    }
    const float inv = 1.0f / (float)C;
    float4 o; o.x = sx * inv; o.y = sy * inv; o.z = sz * inv; o.w = sw * inv;
    reinterpret_cast<float4*>(g_Y)[(size_t)b * S4 + f] = o;
}

// ---------------------------------------------------------------------------
// K2: GEMM1 partials.  Hpart[kc][b][o] = sum_{j in chunk} Y[b][j]*W1[o][j]
// grid (32 kc, 7 o-tiles of 28), block 256.  (R2 configuration.)
// ---------------------------------------------------------------------------
__global__ void k_gemm1(const float* __restrict__ W1) {
    __shared__ float sY[B * 101];        // [b][j]
    __shared__ float sW[KCH * 28];       // [j][o_local]
    int kc = blockIdx.x;
    int ob = blockIdx.y;                 // o base = ob*28
    int kb = kc * KCH;
    int t = threadIdx.x;

    for (int idx = t; idx < B * KCH; idx += 256) {
        int j = idx % KCH, b2 = idx / KCH;
        sY[b2 * 101 + j] = g_Y[b2 * S + kb + j];
    }
    for (int idx = t; idx < KCH * 28; idx += 256) {
        int j = idx % KCH, o = idx / KCH;
        sW[j * 28 + o] = W1[(size_t)(ob * 28 + o) * S + kb + j];
    }
    __syncthreads();

    int b2 = t & 63;
    int og = t >> 6;                     // 0..3, 7 outputs each
    float acc[7];
#pragma unroll
    for (int o = 0; o < 7; o++) acc[o] = 0.f;
#pragma unroll 2
    for (int j = 0; j < KCH; j++) {
        float y = sY[b2 * 101 + j];
        const float* wr = &sW[j * 28 + og * 7];
#pragma unroll
        for (int o = 0; o < 7; o++) acc[o] = fmaf(y, wr[o], acc[o]);
    }
    int base = kc * (B * HID) + b2 * HID + ob * 28 + og * 7;
#pragma unroll
    for (int o = 0; o < 7; o++) g_Hpart[base + o] = acc[o];
}

// ---------------------------------------------------------------------------
// K3: reduce partials + ReLU.  grid 49, block 256
// ---------------------------------------------------------------------------
__global__ void k_redrelu() {
    int idx = blockIdx.x * 256 + threadIdx.x;
    if (idx >= B * HID) return;
    float s = 0.f;
#pragma unroll
    for (int kc = 0; kc < KC; kc++) s += g_Hpart[kc * (B * HID) + idx];
    g_H[idx] = s > 0.f ? s : 0.f;
}

// ---------------------------------------------------------------------------
// K4: GEMM2 + sigmoid.  S[b][n] = sigmoid( sum_j H[b][j]*W2[n][j] )
// grid (98 n-tiles of 32, 4 b-quarters of 16), block 256.  (R2 configuration.)
// ---------------------------------------------------------------------------
__global__ void k_gemm2(const float* __restrict__ W2) {
    __shared__ float sW2[HID * 33];          // [j][n_local]
    __shared__ __align__(8) float sHT[HID * 16];  // [j][b_local]
    int n0 = blockIdx.x * 32;
    int b0 = blockIdx.y * 16;
    int t = threadIdx.x;

    for (int idx = t; idx < HID * 32; idx += 256) {
        int nl = idx / HID, j = idx % HID;       // global read coalesced
        sW2[j * 33 + nl] = W2[(size_t)(n0) * HID + idx];
    }
    for (int idx = t; idx < HID * 16; idx += 256) {
        int b2 = idx & 15, j = idx >> 4;
        sHT[idx] = g_H[(b0 + b2) * HID + j];     // sHT[j*16+b2] == sHT[idx]
    }
    __syncthreads();

    int nl = t & 31;
    int bg = t >> 5;                             // 0..7, 2 b's each
    float a0 = 0.f, a1 = 0.f;
#pragma unroll 4
    for (int j = 0; j < HID; j++) {
        float w = sW2[j * 33 + nl];
        float2 h = *reinterpret_cast<const float2*>(&sHT[j * 16 + bg * 2]);
        a0 = fmaf(h.x, w, a0);
        a1 = fmaf(h.y, w, a1);
    }
    int b = b0 + bg * 2;
    int n = n0 + nl;
    g_S[(size_t)b * S + n]       = 1.0f / (1.0f + expf(-a0));
    g_S[(size_t)(b + 1) * S + n] = 1.0f / (1.0f + expf(-a1));
}

// ---------------------------------------------------------------------------
// K5: exact rank-1568 selection per row + masking (stable-argsort semantics).
// (R2 configuration.)  grid 64, block 256
// ---------------------------------------------------------------------------
__global__ void k_select() {
    __shared__ float sv[S];
    __shared__ unsigned int hist[256];
    __shared__ unsigned int wsum[8];
    __shared__ unsigned int sh_pref, sh_r;
    int b = blockIdx.x, t = threadIdx.x;
    int lane = t & 31, wid = t >> 5;

    for (int i = t; i < S; i += 256) sv[i] = g_S[b * S + i];
    if (t == 0) { sh_pref = 0u; sh_r = KSEL; }
    __syncthreads();

    // radix select: find bit pattern T of the KSEL-th smallest value
    for (int shift = 24; shift >= 0; shift -= 8) {
        hist[t] = 0u;
        __syncthreads();
        unsigned pref = sh_pref;
        unsigned r    = sh_r;
        unsigned hm   = (shift == 24) ? 0u : (0xFFFFFFFFu << (shift + 8));
        for (int i = t; i < S; i += 256) {
            unsigned u = __float_as_uint(sv[i]);
            if ((u & hm) == pref) atomicAdd(&hist[(u >> shift) & 255], 1u);
        }
        __syncthreads();
        unsigned v = hist[t];
        unsigned x = v;
#pragma unroll
        for (int off = 1; off < 32; off <<= 1) {
            unsigned y = __shfl_up_sync(0xFFFFFFFFu, x, off);
            if (lane >= off) x += y;
        }
        if (lane == 31) wsum[wid] = x;
        __syncthreads();
        if (t < 8) {
            unsigned s = wsum[t];
#pragma unroll
            for (int off = 1; off < 8; off <<= 1) {
                unsigned y = __shfl_up_sync(0xFFu, s, off);
                if (t >= off) s += y;
            }
            wsum[t] = s;
        }
        __syncthreads();
        unsigned incl = x + (wid ? wsum[wid - 1] : 0u);
        unsigned excl = incl - v;
        if (v > 0u && r >= excl && r < incl) {   // exactly one thread
            sh_pref = pref | ((unsigned)t << shift);
            sh_r    = r - excl;
        }
        __syncthreads();
    }
    unsigned T    = sh_pref;   // bits of threshold (first KEPT value)
    unsigned rfin = sh_r;      // # of threshold-equal entries (lowest idx) to zero

    // masking: zero u<T; among u==T zero the first rfin by ascending index
    int lo = (t * S) >> 8;
    int hi = ((t + 1) * S) >> 8;
    unsigned cnt = 0;
    for (int i = lo; i < hi; i++)
        cnt += (__float_as_uint(sv[i]) == T) ? 1u : 0u;
    unsigned x = cnt;
#pragma unroll
    for (int off = 1; off < 32; off <<= 1) {
        unsigned y = __shfl_up_sync(0xFFFFFFFFu, x, off);
        if (lane >= off) x += y;
    }
    if (lane == 31) wsum[wid] = x;
    __syncthreads();
    if (t < 8) {
        unsigned s = wsum[t];
#pragma unroll
        for (int off = 1; off < 8; off <<= 1) {
            unsigned y = __shfl_up_sync(0xFFu, s, off);
            if (t >= off) s += y;
        }
        wsum[t] = s;
    }
    __syncthreads();
    unsigned e = x - cnt + (wid ? wsum[wid - 1] : 0u);  // exclusive prefix
    for (int i = lo; i < hi; i++) {
        unsigned u = __float_as_uint(sv[i]);
        float val = sv[i];
        if (u < T) val = 0.f;
        else if (u == T) { if (e < rfin) val = 0.f; e++; }
        g_M[b * S + i] = val;
    }
}

// ---------------------------------------------------------------------------
// K6: broadcast masked row over 256 planes.  grid 1568, block 256.
// Each thread: 1 L2 load + 32 coalesced float4 streaming stores.
// id = (b*8 + cg)*S4 + f  -> warps store 512B-contiguous lines.
// ---------------------------------------------------------------------------
__global__ void k_bcast(float* __restrict__ out) {
    int id = blockIdx.x * 256 + threadIdx.x;     // 0 .. 64*8*784-1
    int f  = id % S4;
    int bc = id / S4;                            // b*8 + cg
    int cg = bc & 7;
    int b  = bc >> 3;
    float4 v = __ldcg(reinterpret_cast<const float4*>(g_M) + (size_t)b * S4 + f);
    float4* op = reinterpret_cast<float4*>(out)
               + (size_t)(b * C + cg * 32) * S4 + f;
#pragma unroll 8
    for (int c = 0; c < 32; c++)
        __stcs(op + (size_t)c * S4, v);
}

// ---------------------------------------------------------------------------
extern "C" void kernel_launch(void* const* d_in, const int* in_sizes, int n_in,
                              void* d_out, int out_size) {
    const float* x  = (const float*)d_in[0];
    const float* W1 = (const float*)d_in[1];
    const float* W2 = (const float*)d_in[2];
    float* out = (float*)d_out;

    k_prefetch<<<512,         256>>>(W1, W2);
    k_pool    <<<dim3(4, B),  256>>>(x);
    k_gemm1   <<<dim3(KC, 7), 256>>>(W1);
    k_redrelu <<<49,          256>>>();
    k_gemm2   <<<dim3(98, 4), 256>>>(W2);
    k_select  <<<B,           256>>>();
    k_bcast   <<<1568,        256>>>(out);
}

// round 5
// speedup vs baseline: 1.7349x; 1.0225x over previous
#include <cuda_runtime.h>
#include <cuda_bf16.h>
#include <math.h>

// Problem constants
#define B    64
#define C    256
#define S    3136          // 56*56
#define S4   784           // S/4
#define HID  196
#define KSEL 1568          // rank of first KEPT element (0-indexed kth smallest)

// K-split for GEMM1
#define KC   32
#define KCH  98            // 3136/32

// Scratch (device globals: no allocation allowed)
__device__ float g_Y[B * S];            // pooled means          [64,3136]
__device__ float g_Hpart[KC * B * HID]; // GEMM1 partials        [32][64*196]
__device__ float g_H[B * HID];          // relu(hidden)          [64,196]
__device__ float g_S[B * S];            // sigmoid outputs       [64,3136]
__device__ float g_M[B * S];            // masked row            [64,3136]
__device__ float g_scratch[128 * 8];    // prefetch sink (never read)

// ---------------------------------------------------------------------------
// K1: channel-mean pool FUSED with W1/W2 L2-prefetch.
// Blocks 0..255: Y[b][s] = mean_c x[b][c][s], float4, __ldcs (evict-first so
//   the 205MB x stream does not evict the weights).
// Blocks 256..383: warm W1+W2 (4.9MB) into L2 via __ldcg, hidden under pool.
// grid 384, block 256
// ---------------------------------------------------------------------------
__global__ void k_pool(const float* __restrict__ x,
                       const float* __restrict__ W1,
                       const float* __restrict__ W2) {
    int blk = blockIdx.x;
    if (blk < 256) {
        int b = blk >> 2;
        int f = (blk & 3) * 256 + threadIdx.x;       // float4 index 0..1023
        if (f >= S4) return;
        const float4* xp = reinterpret_cast<const float4*>(x) + (size_t)b * C * S4 + f;
        float sx = 0.f, sy = 0.f, sz = 0.f, sw = 0.f;
#pragma unroll 16
        for (int c = 0; c < C; c++) {
            float4 v = __ldcs(xp + (size_t)c * S4);
            sx += v.x; sy += v.y; sz += v.z; sw += v.w;
        }
        const float inv = 1.0f / (float)C;
        float4 o; o.x = sx * inv; o.y = sy * inv; o.z = sz * inv; o.w = sw * inv;
        reinterpret_cast<float4*>(g_Y)[(size_t)b * S4 + f] = o;
    } else {
        // prefetch: 128 blocks x 256 threads, ~10 float4 loads each
        const int NF4 = (S * HID) / 4;               // 153664 float4 per matrix
        int t = (blk - 256) * 256 + threadIdx.x;     // 0..32767
        float s = 0.f;
        const float4* w1 = reinterpret_cast<const float4*>(W1);
        const float4* w2 = reinterpret_cast<const float4*>(W2);
        for (int i = t; i < NF4; i += 128 * 256) {
            float4 a = __ldcg(w1 + i);
            float4 b4 = __ldcg(w2 + i);
            s += a.x + a.y + a.z + a.w + b4.x + b4.y + b4.z + b4.w;
        }
#pragma unroll
        for (int off = 16; off > 0; off >>= 1)
            s += __shfl_down_sync(0xFFFFFFFFu, s, off);
        if ((threadIdx.x & 31) == 0)
            g_scratch[(blk - 256) * 8 + (threadIdx.x >> 5)] = s;
    }
}

// ---------------------------------------------------------------------------
// K2: GEMM1 partials.  Hpart[kc][b][o] = sum_{j in chunk} Y[b][j]*W1[o][j]
// grid (32 kc, 7 o-tiles of 28), block 256.  (proven R2/R4 configuration)
// ---------------------------------------------------------------------------
__global__ void k_gemm1(const float* __restrict__ W1) {
    __shared__ float sY[B * 101];        // [b][j]
    __shared__ float sW[KCH * 28];       // [j][o_local]
    int kc = blockIdx.x;
    int ob = blockIdx.y;                 // o base = ob*28
    int kb = kc * KCH;
    int t = threadIdx.x;

    for (int idx = t; idx < B * KCH; idx += 256) {
        int j = idx % KCH, b2 = idx / KCH;
        sY[b2 * 101 + j] = g_Y[b2 * S + kb + j];
    }
    for (int idx = t; idx < KCH * 28; idx += 256) {
        int j = idx % KCH, o = idx / KCH;
        sW[j * 28 + o] = W1[(size_t)(ob * 28 + o) * S + kb + j];
    }
    __syncthreads();

    int b2 = t & 63;
    int og = t >> 6;                     // 0..3, 7 outputs each
    float acc[7];
#pragma unroll
    for (int o = 0; o < 7; o++) acc[o] = 0.f;
#pragma unroll 2
    for (int j = 0; j < KCH; j++) {
        float y = sY[b2 * 101 + j];
        const float* wr = &sW[j * 28 + og * 7];
#pragma unroll
        for (int o = 0; o < 7; o++) acc[o] = fmaf(y, wr[o], acc[o]);
    }
    int base = kc * (B * HID) + b2 * HID + ob * 28 + og * 7;
#pragma unroll
    for (int o = 0; o < 7; o++) g_Hpart[base + o] = acc[o];
}

// ---------------------------------------------------------------------------
// K3: reduce partials + ReLU.  4 threads per output, 8 partials each,
// shuffle-combine.  grid 196, block 256 (12544 outputs x 4 threads).
// ---------------------------------------------------------------------------
__global__ void k_redrelu() {
    int tid = blockIdx.x * 256 + threadIdx.x;
    int g   = tid >> 2;                  // output index 0..12543
    int sub = tid & 3;                   // which quarter of the kc range
    float s = 0.f;
#pragma unroll
    for (int i = 0; i < 8; i++)
        s += g_Hpart[(sub + 4 * i) * (B * HID) + g];
    // combine the 4 sub-lanes (adjacent lanes in the same warp)
    s += __shfl_xor_sync(0xFFFFFFFFu, s, 1);
    s += __shfl_xor_sync(0xFFFFFFFFu, s, 2);
    if (sub == 0)
        g_H[g] = s > 0.f ? s : 0.f;
}

// ---------------------------------------------------------------------------
// K4: GEMM2 + sigmoid.  S[b][n] = sigmoid( sum_j H[b][j]*W2[n][j] )
// grid (98 n-tiles of 32, 4 b-quarters of 16), block 256.  (proven config)
// ---------------------------------------------------------------------------
__global__ void k_gemm2(const float* __restrict__ W2) {
    __shared__ float sW2[HID * 33];          // [j][n_local]
    __shared__ __align__(8) float sHT[HID * 16];  // [j][b_local]
    int n0 = blockIdx.x * 32;
    int b0 = blockIdx.y * 16;
    int t = threadIdx.x;

    for (int idx = t; idx < HID * 32; idx += 256) {
        int nl = idx / HID, j = idx % HID;       // global read coalesced
        sW2[j * 33 + nl] = W2[(size_t)(n0) * HID + idx];
    }
    for (int idx = t; idx < HID * 16; idx += 256) {
        int b2 = idx & 15, j = idx >> 4;
        sHT[idx] = g_H[(b0 + b2) * HID + j];
    }
    __syncthreads();

    int nl = t & 31;
    int bg = t >> 5;                             // 0..7, 2 b's each
    float a0 = 0.f, a1 = 0.f;
#pragma unroll 4
    for (int j = 0; j < HID; j++) {
        float w = sW2[j * 33 + nl];
        float2 h = *reinterpret_cast<const float2*>(&sHT[j * 16 + bg * 2]);
        a0 = fmaf(h.x, w, a0);
        a1 = fmaf(h.y, w, a1);
    }
    int b = b0 + bg * 2;
    int n = n0 + nl;
    g_S[(size_t)b * S + n]       = 1.0f / (1.0f + expf(-a0));
    g_S[(size_t)(b + 1) * S + n] = 1.0f / (1.0f + expf(-a1));
}

// ---------------------------------------------------------------------------
// K5: exact rank-1568 selection per row + masking (stable-argsort semantics).
// grid 64, block 256.  (proven config)
// ---------------------------------------------------------------------------
__global__ void k_select() {
    __shared__ float sv[S];
    __shared__ unsigned int hist[256];
    __shared__ unsigned int wsum[8];
    __shared__ unsigned int sh_pref, sh_r;
    int b = blockIdx.x, t = threadIdx.x;
    int lane = t & 31, wid = t >> 5;

    for (int i = t; i < S; i += 256) sv[i] = g_S[b * S + i];
    if (t == 0) { sh_pref = 0u; sh_r = KSEL; }
    __syncthreads();

    for (int shift = 24; shift >= 0; shift -= 8) {
        hist[t] = 0u;
        __syncthreads();
        unsigned pref = sh_pref;
        unsigned r    = sh_r;
        unsigned hm   = (shift == 24) ? 0u : (0xFFFFFFFFu << (shift + 8));
        for (int i = t; i < S; i += 256) {
            unsigned u = __float_as_uint(sv[i]);
            if ((u & hm) == pref) atomicAdd(&hist[(u >> shift) & 255], 1u);
        }
        __syncthreads();
        unsigned v = hist[t];
        unsigned x = v;
#pragma unroll
        for (int off = 1; off < 32; off <<= 1) {
            unsigned y = __shfl_up_sync(0xFFFFFFFFu, x, off);
            if (lane >= off) x += y;
        }
        if (lane == 31) wsum[wid] = x;
        __syncthreads();
        if (t < 8) {
            unsigned s = wsum[t];
#pragma unroll
            for (int off = 1; off < 8; off <<= 1) {
                unsigned y = __shfl_up_sync(0xFFu, s, off);
                if (t >= off) s += y;
            }
            wsum[t] = s;
        }
        __syncthreads();
        unsigned incl = x + (wid ? wsum[wid - 1] : 0u);
        unsigned excl = incl - v;
        if (v > 0u && r >= excl && r < incl) {   // exactly one thread
            sh_pref = pref | ((unsigned)t << shift);
            sh_r    = r - excl;
        }
        __syncthreads();
    }
    unsigned T    = sh_pref;
    unsigned rfin = sh_r;

    int lo = (t * S) >> 8;
    int hi = ((t + 1) * S) >> 8;
    unsigned cnt = 0;
    for (int i = lo; i < hi; i++)
        cnt += (__float_as_uint(sv[i]) == T) ? 1u : 0u;
    unsigned x = cnt;
#pragma unroll
    for (int off = 1; off < 32; off <<= 1) {
        unsigned y = __shfl_up_sync(0xFFFFFFFFu, x, off);
        if (lane >= off) x += y;
    }
    if (lane == 31) wsum[wid] = x;
    __syncthreads();
    if (t < 8) {
        unsigned s = wsum[t];
#pragma unroll
        for (int off = 1; off < 8; off <<= 1) {
            unsigned y = __shfl_up_sync(0xFFu, s, off);
            if (t >= off) s += y;
        }
        wsum[t] = s;
    }
    __syncthreads();
    unsigned e = x - cnt + (wid ? wsum[wid - 1] : 0u);
    for (int i = lo; i < hi; i++) {
        unsigned u = __float_as_uint(sv[i]);
        float val = sv[i];
        if (u < T) val = 0.f;
        else if (u == T) { if (e < rfin) val = 0.f; e++; }
        g_M[b * S + i] = val;
    }
}

// ---------------------------------------------------------------------------
// K6: broadcast masked row over 256 planes.  grid 1568, block 256.
// Each thread: 1 L2 load + 32 coalesced float4 streaming stores.
// ---------------------------------------------------------------------------
__global__ void k_bcast(float* __restrict__ out) {
    int id = blockIdx.x * 256 + threadIdx.x;     // 0 .. 64*8*784-1
    int f  = id % S4;
    int bc = id / S4;                            // b*8 + cg
    int cg = bc & 7;
    int b  = bc >> 3;
    float4 v = __ldcg(reinterpret_cast<const float4*>(g_M) + (size_t)b * S4 + f);
    float4* op = reinterpret_cast<float4*>(out)
               + (size_t)(b * C + cg * 32) * S4 + f;
#pragma unroll 8
    for (int c = 0; c < 32; c++)
        __stcs(op + (size_t)c * S4, v);
}

// ---------------------------------------------------------------------------
extern "C" void kernel_launch(void* const* d_in, const int* in_sizes, int n_in,
                              void* d_out, int out_size) {
    const float* x  = (const float*)d_in[0];
    const float* W1 = (const float*)d_in[1];
    const float* W2 = (const float*)d_in[2];
    float* out = (float*)d_out;

    k_pool    <<<384,         256>>>(x, W1, W2);
    k_gemm1   <<<dim3(KC, 7), 256>>>(W1);
    k_redrelu <<<196,         256>>>();
    k_gemm2   <<<dim3(98, 4), 256>>>(W2);
    k_select  <<<B,           256>>>();
    k_bcast   <<<1568,        256>>>(out);
}

// round 6
// speedup vs baseline: 1.8973x; 1.0936x over previous
#include <cuda_runtime.h>
#include <cuda_bf16.h>
#include <math.h>

// Problem constants
#define B    64
#define C    256
#define S    3136          // 56*56
#define S4   784           // S/4 (float4 units)
#define S2   1568          // S/2 (float2 units)
#define HID  196
#define HID4 49            // HID/4
#define KSEL 1568          // rank of first KEPT element (0-indexed kth smallest)

// K-split for GEMM1
#define KC   49
#define KCH  64            // 3136/49

// Scratch (device globals: no allocation allowed)
__device__ float g_Yp[2][B * S];        // pooled partial sums (2 c-halves)
__device__ float g_Hpart[KC * B * HID]; // GEMM1 partials        [49][64*196]
__device__ float g_H[B * HID];          // relu(hidden)          [64,196]
__device__ float g_S[B * S];            // sigmoid outputs       [64,3136]
__device__ float g_M[B * S];            // masked row            [64,3136]
__device__ float g_scratch[128 * 8];    // prefetch sink (never read)

// ---------------------------------------------------------------------------
// K1: channel-mean pool (partial, c-split x2) FUSED with W1/W2 L2-prefetch.
// Blocks 0..127:   warm W1+W2 (4.9MB) into L2 via __ldcg (wave-1 scheduled).
// Blocks 128..911: 784 balanced pool blocks; each thread sums one float2
//   column over 128 channels (__ldcs evict-first) into g_Yp[half].
// grid 912, block 256
// ---------------------------------------------------------------------------
__global__ void k_pool(const float* __restrict__ x,
                       const float* __restrict__ W1,
                       const float* __restrict__ W2) {
    int blk = blockIdx.x;
    if (blk < 128) {
        const int NF4 = (S * HID) / 4;               // 153664 float4 per matrix
        int t = blk * 256 + threadIdx.x;             // 0..32767
        float s = 0.f;
        const float4* w1 = reinterpret_cast<const float4*>(W1);
        const float4* w2 = reinterpret_cast<const float4*>(W2);
        for (int i = t; i < NF4; i += 128 * 256) {
            float4 a = __ldcg(w1 + i);
            float4 b4 = __ldcg(w2 + i);
            s += a.x + a.y + a.z + a.w + b4.x + b4.y + b4.z + b4.w;
        }
#pragma unroll
        for (int off = 16; off > 0; off >>= 1)
            s += __shfl_down_sync(0xFFFFFFFFu, s, off);
        if ((threadIdx.x & 31) == 0)
            g_scratch[blk * 8 + (threadIdx.x >> 5)] = s;
    } else {
        int id = (blk - 128) * 256 + threadIdx.x;    // 0..200703
        int half = (id >= B * S2) ? 1 : 0;           // c-half
        int id2 = id - half * (B * S2);              // 0..100351
        int b = id2 / S2;
        int f = id2 - b * S2;                        // float2 column index
        const float2* xp = reinterpret_cast<const float2*>(x)
                         + (size_t)b * C * S2 + (size_t)half * 128 * S2 + f;
        float sx = 0.f, sy = 0.f;
#pragma unroll 16
        for (int c = 0; c < 128; c++) {
            float2 v = __ldcs(xp + (size_t)c * S2);
            sx += v.x; sy += v.y;
        }
        float2 o; o.x = sx; o.y = sy;
        reinterpret_cast<float2*>(g_Yp[half])[(size_t)b * S2 + f] = o;
    }
}

// ---------------------------------------------------------------------------
// K2: GEMM1 partials.  Hpart[kc][b][o] = sum_{j in chunk} Y[b][j]*W1[o][j]
// grid (49 kc, 7 o-tiles of 28), block 256.  All fills float4; Y halves
// combined + scaled by 1/256 here.
// ---------------------------------------------------------------------------
__global__ void k_gemm1(const float* __restrict__ W1) {
    __shared__ float sY[B * 65];         // [b][j] pitch 65 (conflict-free)
    __shared__ float sW[KCH * 28];       // [j][o_local]
    int kc = blockIdx.x;
    int o0 = blockIdx.y * 28;
    int t = threadIdx.x;
    const float inv = 1.0f / 256.0f;

    // Y fill: 64 b x 16 f4 = 1024 f4-pairs, 4 per thread
    const float4* yp0 = reinterpret_cast<const float4*>(g_Yp[0]);
    const float4* yp1 = reinterpret_cast<const float4*>(g_Yp[1]);
    for (int idx = t; idx < B * 16; idx += 256) {
        int b2 = idx >> 4, jq = idx & 15;
        int gi = b2 * S4 + kc * 16 + jq;
        float4 p = yp0[gi];
        float4 q = yp1[gi];
        float* d = &sY[b2 * 65 + jq * 4];
        d[0] = (p.x + q.x) * inv;
        d[1] = (p.y + q.y) * inv;
        d[2] = (p.z + q.z) * inv;
        d[3] = (p.w + q.w) * inv;
    }
    // W fill: 28 rows x 16 f4 = 448 f4, ~1.75 per thread
    const float4* w4 = reinterpret_cast<const float4*>(W1);
    for (int idx = t; idx < 28 * 16; idx += 256) {
        int o = idx >> 4, jq = idx & 15;
        float4 w = w4[(size_t)(o0 + o) * S4 + kc * 16 + jq];
        sW[(jq * 4 + 0) * 28 + o] = w.x;
        sW[(jq * 4 + 1) * 28 + o] = w.y;
        sW[(jq * 4 + 2) * 28 + o] = w.z;
        sW[(jq * 4 + 3) * 28 + o] = w.w;
    }
    __syncthreads();

    int b2 = t & 63;
    int og = t >> 6;                     // 0..3, 7 outputs each
    float acc[7];
#pragma unroll
    for (int o = 0; o < 7; o++) acc[o] = 0.f;
    const float* yr = &sY[b2 * 65];
#pragma unroll 4
    for (int j = 0; j < KCH; j++) {
        float y = yr[j];
        const float* wr = &sW[j * 28 + og * 7];
#pragma unroll
        for (int o = 0; o < 7; o++) acc[o] = fmaf(y, wr[o], acc[o]);
    }
    int base = kc * (B * HID) + b2 * HID + o0 + og * 7;
#pragma unroll
    for (int o = 0; o < 7; o++) g_Hpart[base + o] = acc[o];
}

// ---------------------------------------------------------------------------
// K3: reduce 49 partials + ReLU.  2 threads per output (25/24 slices each),
// shuffle combine.  grid 98, block 256.
// ---------------------------------------------------------------------------
__global__ void k_redrelu() {
    int tid = blockIdx.x * 256 + threadIdx.x;
    int g   = tid >> 1;                  // output index 0..12543
    int sub = tid & 1;
    float s = 0.f;
    for (int i = sub; i < KC; i += 2)
        s += g_Hpart[i * (B * HID) + g];
    s += __shfl_xor_sync(0xFFFFFFFFu, s, 1);
    if (sub == 0)
        g_H[g] = s > 0.f ? s : 0.f;
}

// ---------------------------------------------------------------------------
// K4: GEMM2 + sigmoid.  S[b][n] = sigmoid( sum_j H[b][j]*W2[n][j] )
// grid (98 n-tiles of 32, 4 b-quarters of 16), block 256.  float4 fills.
// ---------------------------------------------------------------------------
__global__ void k_gemm2(const float* __restrict__ W2) {
    __shared__ float sW2[HID * 33];               // [j][n_local]
    __shared__ __align__(8) float sHT[HID * 16];  // [j][b_local]
    int n0 = blockIdx.x * 32;
    int b0 = blockIdx.y * 16;
    int t = threadIdx.x;

    // W2 fill: 32 rows x 49 f4 = 1568 f4, ~6.1 per thread
    const float4* w4 = reinterpret_cast<const float4*>(W2);
    for (int idx = t; idx < 32 * HID4; idx += 256) {
        int nl = idx / HID4, jq = idx - nl * HID4;
        float4 w = w4[(size_t)(n0 + nl) * HID4 + jq];
        sW2[(jq * 4 + 0) * 33 + nl] = w.x;
        sW2[(jq * 4 + 1) * 33 + nl] = w.y;
        sW2[(jq * 4 + 2) * 33 + nl] = w.z;
        sW2[(jq * 4 + 3) * 33 + nl] = w.w;
    }
    // H fill (transposed): 16 rows x 49 f4 = 784 f4, ~3.1 per thread
    const float4* h4 = reinterpret_cast<const float4*>(g_H);
    for (int idx = t; idx < 16 * HID4; idx += 256) {
        int b2 = idx / HID4, jq = idx - b2 * HID4;
        float4 h = h4[(size_t)(b0 + b2) * HID4 + jq];
        sHT[(jq * 4 + 0) * 16 + b2] = h.x;
        sHT[(jq * 4 + 1) * 16 + b2] = h.y;
        sHT[(jq * 4 + 2) * 16 + b2] = h.z;
        sHT[(jq * 4 + 3) * 16 + b2] = h.w;
    }
    __syncthreads();

    int nl = t & 31;
    int bg = t >> 5;                             // 0..7, 2 b's each
    float a0 = 0.f, a1 = 0.f;
#pragma unroll 4
    for (int j = 0; j < HID; j++) {
        float w = sW2[j * 33 + nl];
        float2 h = *reinterpret_cast<const float2*>(&sHT[j * 16 + bg * 2]);
        a0 = fmaf(h.x, w, a0);
        a1 = fmaf(h.y, w, a1);
    }
    int b = b0 + bg * 2;
    int n = n0 + nl;
    g_S[(size_t)b * S + n]       = 1.0f / (1.0f + expf(-a0));
    g_S[(size_t)(b + 1) * S + n] = 1.0f / (1.0f + expf(-a1));
}

// ---------------------------------------------------------------------------
// K5: exact rank-1568 selection per row + masking (stable-argsort semantics).
// grid 64, block 256.  (proven config)
// ---------------------------------------------------------------------------
__global__ void k_select() {
    __shared__ float sv[S];
    __shared__ unsigned int hist[256];
    __shared__ unsigned int wsum[8];
    __shared__ unsigned int sh_pref, sh_r;
    int b = blockIdx.x, t = threadIdx.x;
    int lane = t & 31, wid = t >> 5;

    for (int i = t; i < S; i += 256) sv[i] = g_S[b * S + i];
    if (t == 0) { sh_pref = 0u; sh_r = KSEL; }
    __syncthreads();

    for (int shift = 24; shift >= 0; shift -= 8) {
        hist[t] = 0u;
        __syncthreads();
        unsigned pref = sh_pref;
        unsigned r    = sh_r;
        unsigned hm   = (shift == 24) ? 0u : (0xFFFFFFFFu << (shift + 8));
        for (int i = t; i < S; i += 256) {
            unsigned u = __float_as_uint(sv[i]);
            if ((u & hm) == pref) atomicAdd(&hist[(u >> shift) & 255], 1u);
        }
        __syncthreads();
        unsigned v = hist[t];
        unsigned x = v;
#pragma unroll
        for (int off = 1; off < 32; off <<= 1) {
            unsigned y = __shfl_up_sync(0xFFFFFFFFu, x, off);
            if (lane >= off) x += y;
        }
        if (lane == 31) wsum[wid] = x;
        __syncthreads();
        if (t < 8) {
            unsigned s = wsum[t];
#pragma unroll
            for (int off = 1; off < 8; off <<= 1) {
                unsigned y = __shfl_up_sync(0xFFu, s, off);
                if (t >= off) s += y;
            }
            wsum[t] = s;
        }
        __syncthreads();
        unsigned incl = x + (wid ? wsum[wid - 1] : 0u);
        unsigned excl = incl - v;
        if (v > 0u && r >= excl && r < incl) {   // exactly one thread
            sh_pref = pref | ((unsigned)t << shift);
            sh_r    = r - excl;
        }
        __syncthreads();
    }
    unsigned T    = sh_pref;
    unsigned rfin = sh_r;

    int lo = (t * S) >> 8;
    int hi = ((t + 1) * S) >> 8;
    unsigned cnt = 0;
    for (int i = lo; i < hi; i++)
        cnt += (__float_as_uint(sv[i]) == T) ? 1u : 0u;
    unsigned x = cnt;
#pragma unroll
    for (int off = 1; off < 32; off <<= 1) {
        unsigned y = __shfl_up_sync(0xFFFFFFFFu, x, off);
        if (lane >= off) x += y;
    }
    if (lane == 31) wsum[wid] = x;
    __syncthreads();
    if (t < 8) {
        unsigned s = wsum[t];
#pragma unroll
        for (int off = 1; off < 8; off <<= 1) {
            unsigned y = __shfl_up_sync(0xFFu, s, off);
            if (t >= off) s += y;
        }
        wsum[t] = s;
    }
    __syncthreads();
    unsigned e = x - cnt + (wid ? wsum[wid - 1] : 0u);
    for (int i = lo; i < hi; i++) {
        unsigned u = __float_as_uint(sv[i]);
        float val = sv[i];
        if (u < T) val = 0.f;
        else if (u == T) { if (e < rfin) val = 0.f; e++; }
        g_M[b * S + i] = val;
    }
}

// ---------------------------------------------------------------------------
// K6: broadcast masked row over 256 planes.  grid 1568, block 256.
// Each thread: 1 L2 load + 32 coalesced float4 streaming stores.
// ---------------------------------------------------------------------------
__global__ void k_bcast(float* __restrict__ out) {
    int id = blockIdx.x * 256 + threadIdx.x;     // 0 .. 64*8*784-1
    int f  = id % S4;
    int bc = id / S4;                            // b*8 + cg
    int cg = bc & 7;
    int b  = bc >> 3;
    float4 v = __ldcg(reinterpret_cast<const float4*>(g_M) + (size_t)b * S4 + f);
    float4* op = reinterpret_cast<float4*>(out)
               + (size_t)(b * C + cg * 32) * S4 + f;
#pragma unroll 8
    for (int c = 0; c < 32; c++)
        __stcs(op + (size_t)c * S4, v);
}

// ---------------------------------------------------------------------------
extern "C" void kernel_launch(void* const* d_in, const int* in_sizes, int n_in,
                              void* d_out, int out_size) {
    const float* x  = (const float*)d_in[0];
    const float* W1 = (const float*)d_in[1];
    const float* W2 = (const float*)d_in[2];
    float* out = (float*)d_out;

    k_pool    <<<912,         256>>>(x, W1, W2);
    k_gemm1   <<<dim3(KC, 7), 256>>>(W1);
    k_redrelu <<<98,          256>>>();
    k_gemm2   <<<dim3(98, 4), 256>>>(W2);
    k_select  <<<B,           256>>>();
    k_bcast   <<<1568,        256>>>(out);
}